// round 15
// baseline (speedup 1.0000x reference)
#include <cuda_runtime.h>
#include <cuda_fp16.h>
#include <cstdint>

#define N_NODES 100000
#define HALFN   50000
#define KK 5
#define CC 16
#define EE 3200000
#define PPK (EE / 4)              // 800,000 int4-packs per k
#define PTOT (KK * PPK)           // 4,000,000 packs
#define NT 1024
#define ACC_ROWS 33000
#define ZH_BYTES (HALFN * 2)      // 100,000 B fp16 half-slice
#define ACC_BYTES (ACC_ROWS * 4)  // 132,000 B fp32 accumulator
#define OFF_ACC ZH_BYTES
#define SMEM_TOTAL (ZH_BYTES + ACC_BYTES)   // 232,000 B (<= 232,448 opt-in)

__device__ __half g_Zt[KK * N_NODES];

__device__ __forceinline__ uint32_t s2u(const void* p) {
    uint32_t a;
    asm("{ .reg .u64 t; cvta.to.shared.u64 t, %1; cvt.u32.u64 %0, t; }" : "=r"(a) : "l"(p));
    return a;
}

// Kernel 1 (R9 form — best measured): Z = X @ h (k-major fp16), zero y.
__global__ __launch_bounds__(256) void compute_z_kernel(
    const float* __restrict__ X, const float* __restrict__ h, float* __restrict__ y)
{
    __shared__ float hs[CC * KK];
    if (threadIdx.x < CC * KK) hs[threadIdx.x] = h[threadIdx.x];
    __syncthreads();
    int n = blockIdx.x * blockDim.x + threadIdx.x;
    if (n >= N_NODES) return;
    float x[CC];
    const float4* xp = reinterpret_cast<const float4*>(X + (size_t)n * CC);
#pragma unroll
    for (int i = 0; i < CC / 4; i++) {
        float4 v = xp[i];
        x[4*i+0]=v.x; x[4*i+1]=v.y; x[4*i+2]=v.z; x[4*i+3]=v.w;
    }
#pragma unroll
    for (int k = 0; k < KK; k++) {
        float acc = 0.f;
#pragma unroll
        for (int c = 0; c < CC; c++) acc += x[c] * hs[c * KK + k];
        g_Zt[k * N_NODES + n] = __float2half_rn(acc);
    }
    y[n] = 0.f;
}

// Unpredicated gather from the local fp16 half-slice; out-of-half cols read the
// clamped address 0; the garbage value is killed by the scatter predicate.
__device__ __forceinline__ float gather_half(uint32_t zbase, uint32_t cl) {
    uint32_t za = zbase + (cl < (uint32_t)HALFN ? cl * 2u : 0u);
    unsigned short hb;
    asm volatile("ld.shared.u16 %0, [%1];" : "=h"(hb) : "r"(za));
    return __half2float(__ushort_as_half(hb));
}

// Dual-pipe scatter: smem window -> ATOMS, else -> REDG. No branch.
__device__ __forceinline__ void scatter_dual(uint32_t accbase, float* __restrict__ y,
                                             uint32_t cl, int r, uint32_t acc_start, float s) {
    uint32_t lr = (uint32_t)r - acc_start;            // in-window iff < ACC_ROWS (unsigned wrap)
    uint32_t sa = accbase + (lr < (uint32_t)ACC_ROWS ? lr * 4u : 0u);
    asm volatile(
        "{\n\t.reg .pred pa, ps, pg;\n\t"
        "setp.lt.u32 pa, %0, 50000;\n\t"              // col in this CTA's half
        "setp.lt.and.u32 ps, %1, 33000, pa;\n\t"      // ... and row in window
        "setp.ge.and.u32 pg, %1, 33000, pa;\n\t"      // ... and row out of window
        "@ps red.shared::cta.add.f32 [%2], %4;\n\t"
        "@pg red.global.add.f32 [%3], %4;\n\t}"
        :: "r"(cl), "r"(lr), "r"(sa), "l"(y + r), "f"(s) : "memory");
}

// Kernel 2 (R11 form + v4 vector-REDG flush): col-halved dual-pipe scatter,
// flat pair indexing over all SMs, no software prefetch.
__global__ __launch_bounds__(NT, 1)
void scatter_kernel(const int4* __restrict__ rows, const int4* __restrict__ cols,
                    const float4* __restrict__ vals, float* __restrict__ y)
{
    extern __shared__ __align__(16) char smem[];
    __half* sZ   = reinterpret_cast<__half*>(smem);
    float*  sAcc = reinterpret_cast<float*>(smem + OFF_ACC);
    const uint32_t zbase   = s2u(smem);
    const uint32_t accbase = zbase + OFF_ACC;
    const int tid = threadIdx.x;

    const int pair  = blockIdx.x >> 1;
    const int half  = blockIdx.x & 1;
    const int pairs = gridDim.x >> 1;
    // Window start, aligned to 4 floats so the v4 flush is 16B-aligned.
    const uint32_t acc_start =
        ((uint32_t)(((long long)blockIdx.x * 7321) % (N_NODES - ACC_ROWS + 1))) & ~3u;
    const int half_off = half * HALFN;

    // Zero accumulator once (window is k-independent; flushed once at the end).
    {
        float4* a4 = reinterpret_cast<float4*>(sAcc);
        float4 z4 = make_float4(0.f, 0.f, 0.f, 0.f);
        for (int i = tid; i < ACC_BYTES / 16; i += NT) a4[i] = z4;
    }

    // Contiguous range of ALL packs for this pair (both halves share it; the
    // sibling's duplicate stream read hits L2, not DRAM).
    int p   = (int)(((long long)pair * PTOT) / pairs);
    int end = (int)(((long long)(pair + 1) * PTOT) / pairs);

    while (p < end) {
        int k    = p / PPK;
        int kend = (k + 1) * PPK; if (kend > end) kend = end;

        // (Re)stage fp16 half-slice for k (straddling pairs restage once).
        __syncthreads();
        {
            const int4* src = reinterpret_cast<const int4*>(
                g_Zt + (size_t)k * N_NODES + half_off);
            int4* dst = reinterpret_cast<int4*>(sZ);
            for (int i = tid; i < ZH_BYTES / 16; i += NT) dst[i] = src[i];
        }
        __syncthreads();

        for (int q = p + tid; q < kend; q += NT) {
            int4   r = __ldcg(rows + q);
            int4   c = __ldcg(cols + q);
            float4 v = __ldcg(vals + q);

            uint32_t c0 = (uint32_t)(c.x - half_off);
            uint32_t c1 = (uint32_t)(c.y - half_off);
            uint32_t c2 = (uint32_t)(c.z - half_off);
            uint32_t c3 = (uint32_t)(c.w - half_off);

            float z0 = gather_half(zbase, c0);
            float z1 = gather_half(zbase, c1);
            float z2 = gather_half(zbase, c2);
            float z3 = gather_half(zbase, c3);

            scatter_dual(accbase, y, c0, r.x, acc_start, v.x * z0);
            scatter_dual(accbase, y, c1, r.y, acc_start, v.y * z1);
            scatter_dual(accbase, y, c2, r.z, acc_start, v.z * z2);
            scatter_dual(accbase, y, c3, r.w, acc_start, v.w * z3);
        }
        p = kend;
    }

    // Flush window: coalesced vectorized reduction (red.global.add.v4.f32),
    // unconditional (adding 0.0 is a no-op; no branch, 1/4 the issue slots).
    __syncthreads();
    {
        const float4* a4 = reinterpret_cast<const float4*>(sAcc);
        float* yb = y + acc_start;
        for (int i = tid; i < ACC_ROWS / 4; i += NT) {
            float4 v = a4[i];
            asm volatile("red.global.add.v4.f32 [%0], {%1, %2, %3, %4};"
                         :: "l"(yb + 4 * i), "f"(v.x), "f"(v.y), "f"(v.z), "f"(v.w)
                         : "memory");
        }
    }
}

extern "C" void kernel_launch(void* const* d_in, const int* in_sizes, int n_in,
                              void* d_out, int out_size) {
    const float* X    = (const float*)d_in[0];
    const int*   rows = (const int*)d_in[1];
    const int*   cols = (const int*)d_in[2];
    const float* vals = (const float*)d_in[3];
    const float* h    = (const float*)d_in[4];
    float* y = (float*)d_out;

    {
        int threads = 256;
        int blocks = (N_NODES + threads - 1) / threads;
        compute_z_kernel<<<blocks, threads>>>(X, h, y);
    }
    {
        static int nblk = 0;
        if (nblk == 0) {
            int sms = 0;
            cudaDeviceGetAttribute(&sms, cudaDevAttrMultiProcessorCount, 0);
            if (sms <= 0) sms = 148;
            nblk = (sms / 2) * 2;             // full-width, even (pairs)
            cudaFuncSetAttribute(scatter_kernel,
                                 cudaFuncAttributeMaxDynamicSharedMemorySize,
                                 SMEM_TOTAL);
        }
        scatter_kernel<<<nblk, NT, SMEM_TOTAL>>>(
            (const int4*)rows, (const int4*)cols, (const float4*)vals, y);
    }
}

// round 16
// speedup vs baseline: 1.3199x; 1.3199x over previous
#include <cuda_runtime.h>
#include <cuda_fp16.h>
#include <cstdint>

#define N_NODES 100000
#define HALFN   50000
#define KK 5
#define CC 16
#define EE 3200000
#define PPK (EE / 4)              // 800,000 int4-packs per k
#define NT 1024
#define PAIRS_PER_K 14            // 14 pack-ranges x 2 col-halves = 28 CTAs per k
#define ACC_ROWS 33000
#define ZH_BYTES (HALFN * 2)      // 100,000 B fp16 half-slice
#define ACC_BYTES (ACC_ROWS * 4)  // 132,000 B fp32 accumulator
#define OFF_ACC ZH_BYTES
#define SMEM_TOTAL (ZH_BYTES + ACC_BYTES)   // 232,000 B (<= 232,448 opt-in)

__device__ __half g_Zt[KK * N_NODES];

__device__ __forceinline__ uint32_t s2u(const void* p) {
    uint32_t a;
    asm("{ .reg .u64 t; cvta.to.shared.u64 t, %1; cvt.u32.u64 %0, t; }" : "=r"(a) : "l"(p));
    return a;
}

// Kernel 1: Z = X @ h (k-major fp16), zero y (d_out is poisoned).
__global__ __launch_bounds__(256) void compute_z_kernel(
    const float* __restrict__ X, const float* __restrict__ h, float* __restrict__ y)
{
    __shared__ float hs[CC * KK];
    if (threadIdx.x < CC * KK) hs[threadIdx.x] = h[threadIdx.x];
    __syncthreads();
    int n = blockIdx.x * blockDim.x + threadIdx.x;
    if (n >= N_NODES) return;
    float x[CC];
    const float4* xp = reinterpret_cast<const float4*>(X + (size_t)n * CC);
#pragma unroll
    for (int i = 0; i < CC / 4; i++) {
        float4 v = xp[i];
        x[4*i+0]=v.x; x[4*i+1]=v.y; x[4*i+2]=v.z; x[4*i+3]=v.w;
    }
#pragma unroll
    for (int k = 0; k < KK; k++) {
        float acc = 0.f;
#pragma unroll
        for (int c = 0; c < CC; c++) acc += x[c] * hs[c * KK + k];
        g_Zt[k * N_NODES + n] = __float2half_rn(acc);
    }
    y[n] = 0.f;
}

// Unpredicated gather from the local fp16 half-slice. Out-of-half cols load a
// clamped address; the garbage value is killed by the scatter predicate.
__device__ __forceinline__ float gather_half(uint32_t zbase, uint32_t cl) {
    uint32_t za = zbase + (cl < (uint32_t)HALFN ? cl * 2u : 0u);
    unsigned short hb;
    asm volatile("ld.shared.u16 %0, [%1];" : "=h"(hb) : "r"(za));
    return __half2float(__ushort_as_half(hb));
}

// Predicated dual-pipe scatter: smem window -> ATOMS, else -> REDG. No branch.
__device__ __forceinline__ void scatter_dual(uint32_t accbase, float* __restrict__ y,
                                             uint32_t cl, int r, uint32_t acc_start, float s) {
    uint32_t lr = (uint32_t)r - acc_start;            // in-window iff < ACC_ROWS (unsigned wrap)
    uint32_t sa = accbase + (lr < (uint32_t)ACC_ROWS ? lr * 4u : 0u);
    asm volatile(
        "{\n\t.reg .pred pa, ps, pg;\n\t"
        "setp.lt.u32 pa, %0, 50000;\n\t"     // edge belongs to this CTA's col-half
        "setp.lt.u32 ps, %1, 33000;\n\t"     // row in smem window
        "and.pred ps, ps, pa;\n\t"
        "not.pred pg, ps;\n\t"
        "and.pred pg, pg, pa;\n\t"
        "@ps red.shared::cta.add.f32 [%2], %4;\n\t"
        "@pg red.global.add.f32 [%3], %4;\n\t}"
        :: "r"(cl), "r"(lr), "r"(sa), "l"(y + r), "f"(s) : "memory");
}

// Kernel 2: col-halved dual-pipe scatter. 28 CTAs per k (14 ranges x 2 halves).
__global__ __launch_bounds__(NT, 1)
void scatter_kernel(const int4* __restrict__ rows, const int4* __restrict__ cols,
                    const float4* __restrict__ vals, float* __restrict__ y)
{
    extern __shared__ __align__(16) char smem[];
    __half* sZ   = reinterpret_cast<__half*>(smem);
    float*  sAcc = reinterpret_cast<float*>(smem + OFF_ACC);
    const uint32_t zbase   = s2u(smem);
    const uint32_t accbase = zbase + OFF_ACC;
    const int tid = threadIdx.x;

    const int xx   = blockIdx.x;          // 0..27 ; pair = xx>>1, half = xx&1
    const int k    = blockIdx.y;
    const int pair = xx >> 1;
    const int half = xx & 1;
    const int cta_id = k * (2 * PAIRS_PER_K) + xx;
    const uint32_t acc_start = (uint32_t)(((long long)cta_id * 7321) % (N_NODES - ACC_ROWS + 1));
    const int half_off = half * HALFN;

    // Stage my fp16 half-slice + zero accumulator.
    {
        const int4* src = reinterpret_cast<const int4*>(g_Zt + (size_t)k * N_NODES + half_off);
        int4* dst = reinterpret_cast<int4*>(sZ);
        for (int i = tid; i < ZH_BYTES / 16; i += NT) dst[i] = src[i];
        float4* a4 = reinterpret_cast<float4*>(sAcc);
        float4 z4 = make_float4(0.f, 0.f, 0.f, 0.f);
        for (int i = tid; i < ACC_BYTES / 16; i += NT) a4[i] = z4;
    }
    __syncthreads();

    // Pack range shared by both col-half CTAs of this pair (adjacent blockIdx.x
    // -> concurrent -> the duplicate stream read hits L2, not DRAM).
    int p   = k * PPK + (int)(((long long)pair * PPK) / PAIRS_PER_K);
    int end = k * PPK + (int)(((long long)(pair + 1) * PPK) / PAIRS_PER_K);

    for (int q = p + tid; q < end; q += NT) {
        int4   r = __ldcg(rows + q);
        int4   c = __ldcg(cols + q);
        float4 v = __ldcg(vals + q);

        uint32_t c0 = (uint32_t)(c.x - half_off);
        uint32_t c1 = (uint32_t)(c.y - half_off);
        uint32_t c2 = (uint32_t)(c.z - half_off);
        uint32_t c3 = (uint32_t)(c.w - half_off);

        float z0 = gather_half(zbase, c0);
        float z1 = gather_half(zbase, c1);
        float z2 = gather_half(zbase, c2);
        float z3 = gather_half(zbase, c3);

        scatter_dual(accbase, y, c0, r.x, acc_start, v.x * z0);
        scatter_dual(accbase, y, c1, r.y, acc_start, v.y * z1);
        scatter_dual(accbase, y, c2, r.z, acc_start, v.z * z2);
        scatter_dual(accbase, y, c3, r.w, acc_start, v.w * z3);
    }

    // Flush accumulator window (coalesced; skip zero slots — add of 0 is a no-op).
    __syncthreads();
    float* yb = y + acc_start;
    for (int i = tid; i < ACC_ROWS; i += NT) {
        float v = sAcc[i];
        if (v != 0.f) atomicAdd(yb + i, v);
    }
}

extern "C" void kernel_launch(void* const* d_in, const int* in_sizes, int n_in,
                              void* d_out, int out_size) {
    const float* X    = (const float*)d_in[0];
    const int*   rows = (const int*)d_in[1];
    const int*   cols = (const int*)d_in[2];
    const float* vals = (const float*)d_in[3];
    const float* h    = (const float*)d_in[4];
    float* y = (float*)d_out;

    {
        int threads = 256;
        int blocks = (N_NODES + threads - 1) / threads;
        compute_z_kernel<<<blocks, threads>>>(X, h, y);
    }
    {
        static int inited = 0;
        if (!inited) {
            inited = 1;
            cudaFuncSetAttribute(scatter_kernel,
                                 cudaFuncAttributeMaxDynamicSharedMemorySize,
                                 SMEM_TOTAL);
        }
        dim3 grid(2 * PAIRS_PER_K, KK);    // (28, 5) = 140 CTAs
        scatter_kernel<<<grid, NT, SMEM_TOTAL>>>(
            (const int4*)rows, (const int4*)cols, (const float4*)vals, y);
    }
}

// round 17
// speedup vs baseline: 1.3408x; 1.0159x over previous
#include <cuda_runtime.h>
#include <cuda_fp16.h>
#include <cstdint>

#define N_NODES 100000
#define HALFN   50000
#define KK 5
#define CC 16
#define EE 3200000
#define PPK (EE / 4)              // 800,000 int4-packs per k
#define NT 1024
#define PAIRS_PER_K 14            // 14 pack-ranges x 2 col-halves = 28 CTAs per k
#define ACC_ROWS 33112            // max window: 100000 + 4*33112 = 232448 B opt-in cap
#define ZH_BYTES (HALFN * 2)      // 100,000 B fp16 half-slice
#define ACC_BYTES (ACC_ROWS * 4)  // 132,448 B fp32 accumulator
#define OFF_ACC ZH_BYTES
#define SMEM_TOTAL (ZH_BYTES + ACC_BYTES)   // 232,448 B (= 227 KB opt-in max)

__device__ __half g_Zt[KK * N_NODES];

__device__ __forceinline__ uint32_t s2u(const void* p) {
    uint32_t a;
    asm("{ .reg .u64 t; cvta.to.shared.u64 t, %1; cvt.u32.u64 %0, t; }" : "=r"(a) : "l"(p));
    return a;
}

// Kernel 1: Z = X @ h (k-major fp16), zero y (d_out is poisoned).
__global__ __launch_bounds__(256) void compute_z_kernel(
    const float* __restrict__ X, const float* __restrict__ h, float* __restrict__ y)
{
    __shared__ float hs[CC * KK];
    if (threadIdx.x < CC * KK) hs[threadIdx.x] = h[threadIdx.x];
    __syncthreads();
    int n = blockIdx.x * blockDim.x + threadIdx.x;
    if (n >= N_NODES) return;
    float x[CC];
    const float4* xp = reinterpret_cast<const float4*>(X + (size_t)n * CC);
#pragma unroll
    for (int i = 0; i < CC / 4; i++) {
        float4 v = xp[i];
        x[4*i+0]=v.x; x[4*i+1]=v.y; x[4*i+2]=v.z; x[4*i+3]=v.w;
    }
#pragma unroll
    for (int k = 0; k < KK; k++) {
        float acc = 0.f;
#pragma unroll
        for (int c = 0; c < CC; c++) acc += x[c] * hs[c * KK + k];
        g_Zt[k * N_NODES + n] = __float2half_rn(acc);
    }
    y[n] = 0.f;
}

// Unpredicated gather from the local fp16 half-slice. Out-of-half cols load a
// clamped address; the garbage value is killed by the scatter predicate.
__device__ __forceinline__ float gather_half(uint32_t zbase, uint32_t cl) {
    uint32_t za = zbase + (cl < (uint32_t)HALFN ? cl * 2u : 0u);
    unsigned short hb;
    asm volatile("ld.shared.u16 %0, [%1];" : "=h"(hb) : "r"(za));
    return __half2float(__ushort_as_half(hb));
}

// Predicated dual-pipe scatter: smem window -> ATOMS, else -> REDG. No branch.
__device__ __forceinline__ void scatter_dual(uint32_t accbase, float* __restrict__ y,
                                             uint32_t cl, int r, uint32_t acc_start, float s) {
    uint32_t lr = (uint32_t)r - acc_start;            // in-window iff < ACC_ROWS (unsigned wrap)
    uint32_t sa = accbase + (lr < (uint32_t)ACC_ROWS ? lr * 4u : 0u);
    asm volatile(
        "{\n\t.reg .pred pa, ps, pg;\n\t"
        "setp.lt.u32 pa, %0, 50000;\n\t"     // edge belongs to this CTA's col-half
        "setp.lt.u32 ps, %1, 33112;\n\t"     // row in smem window
        "and.pred ps, ps, pa;\n\t"
        "not.pred pg, ps;\n\t"
        "and.pred pg, pg, pa;\n\t"
        "@ps red.shared::cta.add.f32 [%2], %4;\n\t"
        "@pg red.global.add.f32 [%3], %4;\n\t}"
        :: "r"(cl), "r"(lr), "r"(sa), "l"(y + r), "f"(s) : "memory");
}

// Kernel 2: col-halved dual-pipe scatter. 28 CTAs per k (14 ranges x 2 halves).
__global__ __launch_bounds__(NT, 1)
void scatter_kernel(const int4* __restrict__ rows, const int4* __restrict__ cols,
                    const float4* __restrict__ vals, float* __restrict__ y)
{
    extern __shared__ __align__(16) char smem[];
    __half* sZ   = reinterpret_cast<__half*>(smem);
    float*  sAcc = reinterpret_cast<float*>(smem + OFF_ACC);
    const uint32_t zbase   = s2u(smem);
    const uint32_t accbase = zbase + OFF_ACC;
    const int tid = threadIdx.x;

    const int xx   = blockIdx.x;          // 0..27 ; pair = xx>>1, half = xx&1
    const int k    = blockIdx.y;
    const int pair = xx >> 1;
    const int half = xx & 1;
    const int cta_id = k * (2 * PAIRS_PER_K) + xx;
    const uint32_t acc_start = (uint32_t)(((long long)cta_id * 7321) % (N_NODES - ACC_ROWS + 1));
    const int half_off = half * HALFN;

    // Stage my fp16 half-slice + zero accumulator.
    {
        const int4* src = reinterpret_cast<const int4*>(g_Zt + (size_t)k * N_NODES + half_off);
        int4* dst = reinterpret_cast<int4*>(sZ);
        for (int i = tid; i < ZH_BYTES / 16; i += NT) dst[i] = src[i];
        for (int i = tid; i < ACC_ROWS; i += NT) sAcc[i] = 0.f;
    }
    __syncthreads();

    // Pack range shared by both col-half CTAs of this pair (adjacent blockIdx.x
    // -> concurrent -> the duplicate stream read hits L2, not DRAM).
    int p   = k * PPK + (int)(((long long)pair * PPK) / PAIRS_PER_K);
    int end = k * PPK + (int)(((long long)(pair + 1) * PPK) / PAIRS_PER_K);

    for (int q = p + tid; q < end; q += NT) {
        int4   r = __ldcg(rows + q);
        int4   c = __ldcg(cols + q);
        float4 v = __ldcg(vals + q);

        uint32_t c0 = (uint32_t)(c.x - half_off);
        uint32_t c1 = (uint32_t)(c.y - half_off);
        uint32_t c2 = (uint32_t)(c.z - half_off);
        uint32_t c3 = (uint32_t)(c.w - half_off);

        float z0 = gather_half(zbase, c0);
        float z1 = gather_half(zbase, c1);
        float z2 = gather_half(zbase, c2);
        float z3 = gather_half(zbase, c3);

        scatter_dual(accbase, y, c0, r.x, acc_start, v.x * z0);
        scatter_dual(accbase, y, c1, r.y, acc_start, v.y * z1);
        scatter_dual(accbase, y, c2, r.z, acc_start, v.z * z2);
        scatter_dual(accbase, y, c3, r.w, acc_start, v.w * z3);
    }

    // Flush accumulator window (coalesced; skip zero slots — add of 0 is a no-op).
    __syncthreads();
    float* yb = y + acc_start;
    for (int i = tid; i < ACC_ROWS; i += NT) {
        float v = sAcc[i];
        if (v != 0.f) atomicAdd(yb + i, v);
    }
}

extern "C" void kernel_launch(void* const* d_in, const int* in_sizes, int n_in,
                              void* d_out, int out_size) {
    const float* X    = (const float*)d_in[0];
    const int*   rows = (const int*)d_in[1];
    const int*   cols = (const int*)d_in[2];
    const float* vals = (const float*)d_in[3];
    const float* h    = (const float*)d_in[4];
    float* y = (float*)d_out;

    {
        int threads = 256;
        int blocks = (N_NODES + threads - 1) / threads;
        compute_z_kernel<<<blocks, threads>>>(X, h, y);
    }
    {
        static int inited = 0;
        if (!inited) {
            inited = 1;
            cudaFuncSetAttribute(scatter_kernel,
                                 cudaFuncAttributeMaxDynamicSharedMemorySize,
                                 SMEM_TOTAL);
        }
        dim3 grid(2 * PAIRS_PER_K, KK);    // (28, 5) = 140 CTAs
        scatter_kernel<<<grid, NT, SMEM_TOTAL>>>(
            (const int4*)rows, (const int4*)cols, (const float4*)vals, y);
    }
}